// round 16
// baseline (speedup 1.0000x reference)
#include <cuda_runtime.h>

#define NN 50000
#define EE 800000
#define ET 850000   // EE + NN self-loops
#define SB 512      // scan block size
#define NB ((NN + SB - 1) / SB)   // 98 scan blocks

// ---------------- scratch (device globals; no runtime allocation) ----------
__device__ int   g_deg[NN];
__device__ int   g_cur[NN];
__device__ int   g_off[NN + 1];
__device__ float g_dis[NN];
__device__ int   g_part[NB];
__device__ int2  g_srcw[ET];            // (src index, weight bits) packed
__device__ float g_s[NN];               // A·1
__device__ float g_s2[NN];              // A²·1
__device__ float g_C[96 * 32];          // W2·W3·W4
__device__ float g_v2[32];              // b2·W3·W4
__device__ float g_v3[32];              // b3·W4
__device__ float g_bufA[(size_t)NN * 128];
__device__ float g_bufB[(size_t)NN * 128];

// Compile-time buffer selector (no host-side symbol lookup).
enum Which { A_, B_, X_ };
template <Which W>
__device__ __forceinline__ const float* inbuf(const float* ext) {
    if constexpr (W == A_) return g_bufA;
    else if constexpr (W == B_) return g_bufB;
    else return ext;
}
template <Which W>
__device__ __forceinline__ float* outbuf(float* ext) {
    if constexpr (W == A_) return g_bufA;
    else if constexpr (W == B_) return g_bufB;
    else return ext;
}

// ---------------- graph prep ------------------------------------------------
// edge_index is int32 (JAX x64 disabled). Count-only pass.
__global__ void k_count(const int* __restrict__ ei) {
    int e = blockIdx.x * blockDim.x + threadIdx.x;
    if (e >= EE) return;
    int c = ei[EE + e];
    if ((unsigned)c >= NN) c = 0;   // never trap on bad data
    atomicAdd(&g_deg[c], 1);
}

// per-block sums of (deg[i]+1)
__global__ __launch_bounds__(SB) void k_scan1() {
    __shared__ int s[SB];
    int t = threadIdx.x;
    int i = blockIdx.x * SB + t;
    s[t] = (i < NN) ? (g_deg[i] + 1) : 0;
    __syncthreads();
#pragma unroll
    for (int o = SB / 2; o > 0; o >>= 1) {
        if (t < o) s[t] += s[t + o];
        __syncthreads();
    }
    if (t == 0) g_part[blockIdx.x] = s[0];
}

// scan of partials (redundant per block) + local scan + write g_off, g_dis
__global__ __launch_bounds__(SB) void k_scan3() {
    __shared__ int ps[128];
    __shared__ int s[SB];
    int t = threadIdx.x;
    if (t < 128) ps[t] = (t < NB) ? g_part[t] : 0;
    __syncthreads();
#pragma unroll
    for (int o = 1; o < 128; o <<= 1) {
        int u = 0;
        if (t < 128 && t >= o) u = ps[t - o];
        __syncthreads();
        if (t < 128) ps[t] += u;
        __syncthreads();
    }
    int base = ps[blockIdx.x] - g_part[blockIdx.x];   // exclusive prefix
    if (blockIdx.x == 0 && t == 0) g_off[NN] = ET;

    int i = blockIdx.x * SB + t;
    int d = (i < NN) ? g_deg[i] : 0;
    int v = (i < NN) ? (d + 1) : 0;
    s[t] = v;
    __syncthreads();
#pragma unroll
    for (int o = 1; o < SB; o <<= 1) {
        int u = (t >= o) ? s[t - o] : 0;
        __syncthreads();
        s[t] += u;
        __syncthreads();
    }
    if (i < NN) {
        g_off[i] = base + s[t] - v;
        g_dis[i] = rsqrtf((float)(d + 1));
    }
}

// fill CSR: edges (read ei directly) + self loops; one packed 8B store/edge
__global__ void k_fillself(const int* __restrict__ ei) {
    int e = blockIdx.x * blockDim.x + threadIdx.x;
    if (e < EE) {
        int r = ei[e];
        int c = ei[EE + e];
        if ((unsigned)r >= NN) r = 0;
        if ((unsigned)c >= NN) c = 0;
        int p = atomicAdd(&g_cur[c], 1);
        float w = g_dis[r] * g_dis[c];
        g_srcw[g_off[c] + p] = make_int2(r, __float_as_int(w));
    } else if (e < EE + NN) {
        int n = e - EE;
        float d = g_dis[n];
        g_srcw[g_off[n + 1] - 1] = make_int2(n, __float_as_int(d * d));
    }
}

// ---------------- weight precompute: C=W2(W3W4), v2=b2(W3W4), v3=b3W4 ------
__global__ __launch_bounds__(512) void k_wprep(const float* __restrict__ W2,
                                               const float* __restrict__ W3,
                                               const float* __restrict__ W4,
                                               const float* __restrict__ b2,
                                               const float* __restrict__ b3) {
    __shared__ float Ts[128 * 32];   // W3·W4
    int t = threadIdx.x;
    for (int i = t; i < 128 * 32; i += 512) {
        int k = i >> 5, o = i & 31;
        float sum = 0.f;
        for (int j = 0; j < 64; j++) sum += W3[k * 64 + j] * W4[j * 32 + o];
        Ts[i] = sum;
    }
    if (t < 32) {
        float sum = 0.f;
        for (int j = 0; j < 64; j++) sum += b3[j] * W4[j * 32 + t];
        g_v3[t] = sum;
    }
    __syncthreads();
    for (int i = t; i < 96 * 32; i += 512) {
        int k = i >> 5, o = i & 31;
        float sum = 0.f;
        for (int j = 0; j < 128; j++) sum += W2[k * 128 + j] * Ts[j * 32 + o];
        g_C[i] = sum;
    }
    if (t < 32) {
        float sum = 0.f;
        for (int j = 0; j < 128; j++) sum += b2[j] * Ts[j * 32 + t];
        g_v2[t] = sum;
    }
}

// ---------------- scalar aggregation (F=29) + replay cleanup ----------------
template <int F, bool BIAS, bool CLEAN, Which SRC, Which DST>
__global__ __launch_bounds__(256) void k_agg(const float* __restrict__ ext_in,
                                             const float* __restrict__ b,
                                             float* __restrict__ ext_out) {
    const float* __restrict__ h = inbuf<SRC>(ext_in);
    float* __restrict__ out = outbuf<DST>(ext_out);
    constexpr int NACC = (F + 31) / 32;
    int warp = (blockIdx.x * blockDim.x + threadIdx.x) >> 5;
    int lane = threadIdx.x & 31;
    if (warp >= NN) return;
    int n = warp;
    if (CLEAN && lane == 0) { g_deg[n] = 0; g_cur[n] = 0; }  // for next replay
    int s = g_off[n], e = g_off[n + 1];
    float acc[NACC];
#pragma unroll
    for (int j = 0; j < NACC; j++) acc[j] = 0.f;
    for (int i = s; i < e; i++) {
        int2 sw = g_srcw[i];
        int src = sw.x;
        float w = __int_as_float(sw.y);
        const float* hp = h + (size_t)src * F;
#pragma unroll
        for (int j = 0; j < NACC; j++) {
            int f = lane + 32 * j;
            if (f < F) acc[j] += w * __ldg(hp + f);
        }
    }
    float* op = out + (size_t)n * F;
#pragma unroll
    for (int j = 0; j < NACC; j++) {
        int f = lane + 32 * j;
        if (f < F) op[f] = acc[j] + (BIAS ? b[f] : 0.f);
    }
}

// ---------------- 32-wide aggregation passes of the collapsed layers --------
// MODE 1: t = A·u,  also s  = A·1   (Σw per node)
// MODE 2: t = A·t1, also s2 = A·s   (Σ w·s[src])
// MODE 3: t = A·t2, epilogue out = t + s2·v2 + s·v3 + b4
template <int MODE, Which SRC, Which DST>
__global__ __launch_bounds__(256) void k_agg32(const float* __restrict__ ext_in,
                                               const float* __restrict__ b4,
                                               float* __restrict__ ext_out) {
    const float* __restrict__ h = inbuf<SRC>(ext_in);
    float* __restrict__ out = outbuf<DST>(ext_out);
    int warp = (blockIdx.x * blockDim.x + threadIdx.x) >> 5;
    int lane = threadIdx.x & 31;
    if (warp >= NN) return;
    int g = lane >> 3;       // 4 edge-groups of 8 lanes
    int q = lane & 7;        // float4 index within the 32-float row
    int s0 = g_off[warp], e0 = g_off[warp + 1];
    float4 acc = make_float4(0.f, 0.f, 0.f, 0.f);
    float ws = 0.f;
    for (int i = s0 + g; i < e0; i += 4) {
        int2 sw = g_srcw[i];
        float w = __int_as_float(sw.y);
        float4 v = __ldg((const float4*)(h + (size_t)sw.x * 32) + q);
        acc.x += w * v.x; acc.y += w * v.y;
        acc.z += w * v.z; acc.w += w * v.w;
        if constexpr (MODE == 1) ws += w;
        if constexpr (MODE == 2) ws += w * __ldg(&g_s[sw.x]);
    }
#pragma unroll
    for (int off = 8; off <= 16; off <<= 1) {
        acc.x += __shfl_xor_sync(0xffffffffu, acc.x, off);
        acc.y += __shfl_xor_sync(0xffffffffu, acc.y, off);
        acc.z += __shfl_xor_sync(0xffffffffu, acc.z, off);
        acc.w += __shfl_xor_sync(0xffffffffu, acc.w, off);
        if constexpr (MODE == 1 || MODE == 2)
            ws += __shfl_xor_sync(0xffffffffu, ws, off);
    }
    if constexpr (MODE == 1) { if (lane == 0) g_s[warp] = ws; }
    if constexpr (MODE == 2) { if (lane == 0) g_s2[warp] = ws; }
    if (g == 0) {
        if constexpr (MODE == 3) {
            float ss = g_s[warp], ss2 = g_s2[warp];
            float4 v2q = *(const float4*)&g_v2[q * 4];
            float4 v3q = *(const float4*)&g_v3[q * 4];
            float4 b4q = __ldg((const float4*)b4 + q);
            acc.x += ss2 * v2q.x + ss * v3q.x + b4q.x;
            acc.y += ss2 * v2q.y + ss * v3q.y + b4q.y;
            acc.z += ss2 * v2q.z + ss * v3q.z + b4q.z;
            acc.w += ss2 * v2q.w + ss * v3q.w + b4q.w;
        }
        ((float4*)(out + (size_t)warp * 32))[q] = acc;
    }
}

// ---------------- tiled GEMM: out[n][o] = bias + sum_k x[n][k]*W[k][o] ------
// 128-node x TN-output tile per 256-thread block; W slice loaded once per
// block. Weight inner loads SCALAR (R10: wide weight LDS regresses).
// WFC selects g_C (device-global precomputed W2W3W4) as the weight source.
template <int IN, int OUT, int NOB, bool BIAS, bool RELU, bool WFC, Which SRC, Which DST>
__global__ __launch_bounds__(256) void k_gemm_t(const float* __restrict__ ext_in,
                                                const float* __restrict__ W,
                                                const float* __restrict__ b,
                                                float* __restrict__ ext_out) {
    constexpr int TN  = OUT / NOB;
    constexpr int VN  = TN / 16;
    constexpr int KT  = 16;
    constexpr int INP = ((IN + KT - 1) / KT) * KT;
    const float* __restrict__ x = inbuf<SRC>(ext_in);
    const float* __restrict__ Wp = WFC ? (const float*)g_C : W;
    float* __restrict__ out = outbuf<DST>(ext_out);

    __shared__ float Xs[KT][128];
    __shared__ float Wsm[INP][TN];

    int t  = threadIdx.x;
    int tx = t & 15, ty = t >> 4;
    int mB = blockIdx.x * 128;
    int oB = blockIdx.y * TN;

    for (int i = t; i < INP * TN; i += 256) {
        int k = i / TN, o = i % TN;
        Wsm[k][o] = (k < IN) ? Wp[k * OUT + oB + o] : 0.f;
    }

    float acc[8][VN];
#pragma unroll
    for (int i = 0; i < 8; i++)
#pragma unroll
        for (int j = 0; j < VN; j++) acc[i][j] = 0.f;

    int mLoad = t & 127;
    int c8    = (t >> 7) * 8;
    const float* xrow = x + (size_t)(mB + mLoad) * IN;
    bool mvalid = (mB + mLoad) < NN;

    for (int kb = 0; kb < INP; kb += KT) {
        float4 v0 = make_float4(0.f, 0.f, 0.f, 0.f);
        float4 v1 = make_float4(0.f, 0.f, 0.f, 0.f);
        if (mvalid) {
            int k0 = kb + c8;
            if constexpr (IN % 4 == 0) {
                v0 = *(const float4*)(xrow + k0);
                v1 = *(const float4*)(xrow + k0 + 4);
            } else {
                if (k0 + 0 < IN) v0.x = xrow[k0 + 0];
                if (k0 + 1 < IN) v0.y = xrow[k0 + 1];
                if (k0 + 2 < IN) v0.z = xrow[k0 + 2];
                if (k0 + 3 < IN) v0.w = xrow[k0 + 3];
                if (k0 + 4 < IN) v1.x = xrow[k0 + 4];
                if (k0 + 5 < IN) v1.y = xrow[k0 + 5];
                if (k0 + 6 < IN) v1.z = xrow[k0 + 6];
                if (k0 + 7 < IN) v1.w = xrow[k0 + 7];
            }
        }
        __syncthreads();
        Xs[c8 + 0][mLoad] = v0.x;
        Xs[c8 + 1][mLoad] = v0.y;
        Xs[c8 + 2][mLoad] = v0.z;
        Xs[c8 + 3][mLoad] = v0.w;
        Xs[c8 + 4][mLoad] = v1.x;
        Xs[c8 + 5][mLoad] = v1.y;
        Xs[c8 + 6][mLoad] = v1.z;
        Xs[c8 + 7][mLoad] = v1.w;
        __syncthreads();
#pragma unroll
        for (int kk = 0; kk < KT; kk++) {
            float4 xa = *(const float4*)&Xs[kk][ty * 8];
            float4 xb = *(const float4*)&Xs[kk][ty * 8 + 4];
            float wv[VN];
#pragma unroll
            for (int j = 0; j < VN; j++) wv[j] = Wsm[kb + kk][tx * VN + j];
#pragma unroll
            for (int j = 0; j < VN; j++) {
                acc[0][j] += xa.x * wv[j];
                acc[1][j] += xa.y * wv[j];
                acc[2][j] += xa.z * wv[j];
                acc[3][j] += xa.w * wv[j];
                acc[4][j] += xb.x * wv[j];
                acc[5][j] += xb.y * wv[j];
                acc[6][j] += xb.z * wv[j];
                acc[7][j] += xb.w * wv[j];
            }
        }
    }

#pragma unroll
    for (int i = 0; i < 8; i++) {
        int m = mB + ty * 8 + i;
        if (m < NN) {
#pragma unroll
            for (int j = 0; j < VN; j++) {
                int o = oB + tx * VN + j;
                float vv = acc[i][j] + (BIAS ? __ldg(b + o) : 0.f);
                out[(size_t)m * OUT + o] = RELU ? fmaxf(vv, 0.f) : vv;
            }
        }
    }
}

// ---------------- launch ----------------------------------------------------
static inline int ceil_div(int a, int b) { return (a + b - 1) / b; }

extern "C" void kernel_launch(void* const* d_in, const int* in_sizes, int n_in,
                              void* d_out, int out_size) {
    const float* x  = (const float*)d_in[0];
    const int*   ei = (const int*)d_in[1];   // int32 edge_index (2, E)
    const float* W1 = (const float*)d_in[2]; const float* b1 = (const float*)d_in[3];
    const float* W2 = (const float*)d_in[4]; const float* b2 = (const float*)d_in[5];
    const float* W3 = (const float*)d_in[6]; const float* b3 = (const float*)d_in[7];
    const float* W4 = (const float*)d_in[8]; const float* b4 = (const float*)d_in[9];
    float* out = (float*)d_out;

    const int TB = 256;
    const int gE  = ceil_div(EE, TB);
    const int gET = ceil_div(ET, TB);
    const int gW  = ceil_div(NN, TB / 32);   // one warp per node
    const int gM  = ceil_div(NN, 128);       // gemm node-blocks (391)

    // weight precompute (one block) + graph prep
    k_wprep<<<1, 512>>>(W2, W3, W4, b2, b3);
    k_count<<<gE, TB>>>(ei);
    k_scan1<<<NB, SB>>>();
    k_scan3<<<NB, SB>>>();
    k_fillself<<<gET, TB>>>(ei);

    // layer 1: h1 = relu((A x) W1 + b1)
    k_agg<29, false, true, X_, A_><<<gW, TB>>>(x, nullptr, nullptr);
    k_gemm_t<29, 96, 2, true, true, false, A_, B_>
        <<<dim3(gM, 2), TB>>>(nullptr, W1, b1, nullptr);

    // collapsed layers 2-4:
    // u = h1·C ; t = A u (+s) ; t = A t (+s2) ; out = A t + s2·v2 + s·v3 + b4
    k_gemm_t<96, 32, 1, false, false, true, B_, A_>
        <<<dim3(gM, 1), TB>>>(nullptr, nullptr, nullptr, nullptr);
    k_agg32<1, A_, B_><<<gW, TB>>>(nullptr, nullptr, nullptr);
    k_agg32<2, B_, A_><<<gW, TB>>>(nullptr, nullptr, nullptr);
    k_agg32<3, A_, X_><<<gW, TB>>>(nullptr, b4, out);

    (void)in_sizes; (void)n_in; (void)out_size;
}